// round 4
// baseline (speedup 1.0000x reference)
#include <cuda_runtime.h>
#include <cstdint>

// Problem constants
#define BQ    2
#define NPT   65536
#define KN    16
#define CIN   64
#define CADD  3
#define CTOT  67          // CIN + CADD
#define CPAD  68          // padded
#define CMID  16
#define INF   1072        // CTOT * CMID
#define COUT  128
#define NPTS  (BQ * NPT)  // 131072 total points

// Scratch for pconv: [NPTS][INF] fp32 = 536 MB (static __device__, allowed)
__device__ float g_pconv[(size_t)NPTS * INF];

// Index dtype flag: 1 if neighbor_inds is int64-layout, 0 if int32-layout
__device__ int g_idx_is64;

// ---------------------------------------------------------------------------
// Packed f32x2 helpers (sm_100+; ptxas never auto-fuses these from C++)
// ---------------------------------------------------------------------------
__device__ __forceinline__ unsigned long long pack2(float lo, float hi) {
    unsigned long long r;
    asm("mov.b64 %0, {%1, %2};" : "=l"(r) : "f"(lo), "f"(hi));
    return r;
}
__device__ __forceinline__ void unpack2(unsigned long long v, float& lo, float& hi) {
    asm("mov.b64 {%0, %1}, %2;" : "=f"(lo), "=f"(hi) : "l"(v));
}
__device__ __forceinline__ void ffma2(unsigned long long& d,
                                      unsigned long long a,
                                      unsigned long long b) {
    asm("fma.rn.f32x2 %0, %1, %2, %0;" : "+l"(d) : "l"(a), "l"(b));
}

// ---------------------------------------------------------------------------
// Kernel 0: detect index dtype. Index values are in [0, 65536), so if the
// buffer holds int64, every odd 32-bit word (high half) of the first 16
// elements is zero. If int32, odd words are random indices — all 16 being
// zero has probability ~(1/65536)^16. Reads 128 bytes, in-bounds for either
// dtype (min possible allocation is 8 MB). Deterministic for fixed inputs.
// ---------------------------------------------------------------------------
__global__ void detect_idx_kernel(const int* __restrict__ idx_raw)
{
    if (threadIdx.x == 0 && blockIdx.x == 0) {
        int nz = 0;
#pragma unroll
        for (int i = 1; i < 32; i += 2) nz |= idx_raw[i];
        g_idx_is64 = (nz == 0) ? 1 : 0;
    }
}

// ---------------------------------------------------------------------------
// Kernel 1: gather + weighted neighbor reduction.
// One warp per point; 4 points per 128-thread block.
// pconv[p][c*16+j] = sum_k feat[k][c] * w[k][j]
// ---------------------------------------------------------------------------
__global__ void __launch_bounds__(128, 8)
pconv_kernel(const float* __restrict__ input_feat,
             const int* __restrict__ nbr_raw,
             const float* __restrict__ wnet,
             const float* __restrict__ addf)
{
    const int warp = threadIdx.x >> 5;     // 0..3
    const int lane = threadIdx.x & 31;
    const int p = blockIdx.x * 4 + warp;   // point index, grid sized exactly
    const int b = p >> 16;                 // p / NPT

    __shared__ __align__(16) float fs[4][KN][CPAD];  // feat, padded to 68
    __shared__ __align__(16) float ws[4][KN][CMID];  // weightnet per point

    const float* featbase = input_feat + (size_t)b * NPT * CIN;
    const float* wp = wnet + (size_t)p * KN * CMID;
    const float* ap = addf + (size_t)p * KN * CADD;

    // Load weightnet: 256 contiguous floats -> 64 float4, 2 per lane
    {
        const float4* w4 = (const float4*)wp;
        float4* s4 = (float4*)(&ws[warp][0][0]);
        s4[lane]      = w4[lane];
        s4[lane + 32] = w4[lane + 32];
    }

    // Read neighbor indices with detected dtype stride; clamp for safety
    // (clamp makes every gather address in-bounds regardless of data).
    const int stride = g_idx_is64 ? 2 : 1;          // 32-bit words per element
    const int* inds = nbr_raw + (size_t)p * KN * stride;
    int myidx = 0;
    if (lane < KN) {
        myidx = inds[lane * stride];                // little-endian low word
        myidx = min(max(myidx, 0), NPT - 1);
    }

    // Gather neighbor rows (each row 256B, 2 coalesced 128B loads per k)
#pragma unroll 4
    for (int k = 0; k < KN; ++k) {
        int r = __shfl_sync(0xffffffffu, myidx, k);
        const float* src = featbase + (size_t)r * CIN;
        fs[warp][k][lane]      = src[lane];
        fs[warp][k][lane + 32] = src[lane + 32];
    }
    // Additional features (3 per k)
    if (lane < KN) {
        fs[warp][lane][64] = ap[lane * 3 + 0];
        fs[warp][lane][65] = ap[lane * 3 + 1];
        fs[warp][lane][66] = ap[lane * 3 + 2];
    }
    __syncwarp();

    // Each lane owns c = lane, lane+32, (lane+64 if lane<3)
    float acc0[CMID], acc1[CMID], acc2[CMID];
#pragma unroll
    for (int j = 0; j < CMID; ++j) { acc0[j] = 0.f; acc1[j] = 0.f; acc2[j] = 0.f; }

    const bool has_c2 = (lane < 3);
#pragma unroll
    for (int k = 0; k < KN; ++k) {
        float wk[CMID];
#pragma unroll
        for (int j = 0; j < CMID; ++j) wk[j] = ws[warp][k][j];
        float f0 = fs[warp][k][lane];
        float f1 = fs[warp][k][lane + 32];
        float f2 = has_c2 ? fs[warp][k][lane + 64] : 0.f;
#pragma unroll
        for (int j = 0; j < CMID; ++j) {
            acc0[j] += f0 * wk[j];
            acc1[j] += f1 * wk[j];
            acc2[j] += f2 * wk[j];
        }
    }

    // Write pconv row (row base 4288B -> 16B-aligned; blocks of 16 floats)
    float* outp = g_pconv + (size_t)p * INF;
#pragma unroll
    for (int q = 0; q < 4; ++q) {
        ((float4*)(outp + (size_t)lane * CMID))[q]        = *(float4*)(&acc0[q * 4]);
        ((float4*)(outp + (size_t)(lane + 32) * CMID))[q] = *(float4*)(&acc1[q * 4]);
    }
    if (has_c2) {
#pragma unroll
        for (int q = 0; q < 4; ++q)
            ((float4*)(outp + (size_t)(lane + 64) * CMID))[q] = *(float4*)(&acc2[q * 4]);
    }
}

// ---------------------------------------------------------------------------
// Kernel 2: out[M=131072, 128] = pconv[M, 1072] @ W[128, 1072]^T + bias
// 128x128 CTA tile, Ks=8, double-buffered smem, 256 threads, 8x8 micro-tile
// computed with packed fma.rn.f32x2 (2 fp32 FMA per issue slot).
// ---------------------------------------------------------------------------
#define MS 128
#define KS 8
#define SPAD 132   // padded smem row (conflict-free, rows stay 16B-aligned)
#define NKT (INF / KS)   // 134 k-tiles

__global__ void __launch_bounds__(256, 2)
gemm_kernel(const float* __restrict__ W,
            const float* __restrict__ bias,
            float* __restrict__ out)
{
    __shared__ __align__(16) float As[2][KS][SPAD];
    __shared__ __align__(16) float Bs[2][KS][SPAD];

    const int t  = threadIdx.x;          // 0..255
    const int tx = t & 15;               // n-dir thread (8 cols each)
    const int ty = t >> 4;               // m-dir thread (8 rows each)
    const int m0 = blockIdx.x * MS;

    // Global load mapping: each thread loads one float4 of A and one of B
    const int lr = t >> 1;               // row in tile (0..127)
    const int lq = (t & 1) * 4;          // k offset (0 or 4)
    const float* aptr = g_pconv + (size_t)(m0 + lr) * INF + lq;
    const float* bptr = W + (size_t)lr * INF + lq;

    // 8x8 accumulator as 8x4 packed f32x2 pairs
    unsigned long long acc[8][4];
#pragma unroll
    for (int i = 0; i < 8; ++i)
#pragma unroll
        for (int j = 0; j < 4; ++j) acc[i][j] = 0ull;

    // Prologue: load tile 0 into buffer 0
    {
        float4 av = *(const float4*)(aptr + 0);
        float4 bv = *(const float4*)(bptr + 0);
        As[0][lq + 0][lr] = av.x; As[0][lq + 1][lr] = av.y;
        As[0][lq + 2][lr] = av.z; As[0][lq + 3][lr] = av.w;
        Bs[0][lq + 0][lr] = bv.x; Bs[0][lq + 1][lr] = bv.y;
        Bs[0][lq + 2][lr] = bv.z; Bs[0][lq + 3][lr] = bv.w;
    }
    __syncthreads();

    for (int kt = 0; kt < NKT; ++kt) {
        const int cur = kt & 1;
        const int nxt = cur ^ 1;

        // Prefetch next tile to registers (overlaps with compute below)
        float4 av, bv;
        const bool have_next = (kt + 1 < NKT);
        if (have_next) {
            const int k0 = (kt + 1) * KS;
            av = *(const float4*)(aptr + k0);
            bv = *(const float4*)(bptr + k0);
        }

        // Compute on current buffer
#pragma unroll
        for (int kk = 0; kk < KS; ++kk) {
            float a[8], bb[8];
            *(float4*)(&a[0])  = *(const float4*)(&As[cur][kk][ty * 8 + 0]);
            *(float4*)(&a[4])  = *(const float4*)(&As[cur][kk][ty * 8 + 4]);
            *(float4*)(&bb[0]) = *(const float4*)(&Bs[cur][kk][tx * 8 + 0]);
            *(float4*)(&bb[4]) = *(const float4*)(&Bs[cur][kk][tx * 8 + 4]);

            unsigned long long bp[4];
#pragma unroll
            for (int j = 0; j < 4; ++j) bp[j] = pack2(bb[2 * j], bb[2 * j + 1]);
#pragma unroll
            for (int i = 0; i < 8; ++i) {
                unsigned long long ad = pack2(a[i], a[i]);
#pragma unroll
                for (int j = 0; j < 4; ++j) ffma2(acc[i][j], ad, bp[j]);
            }
        }

        if (have_next) {
            As[nxt][lq + 0][lr] = av.x; As[nxt][lq + 1][lr] = av.y;
            As[nxt][lq + 2][lr] = av.z; As[nxt][lq + 3][lr] = av.w;
            Bs[nxt][lq + 0][lr] = bv.x; Bs[nxt][lq + 1][lr] = bv.y;
            Bs[nxt][lq + 2][lr] = bv.z; Bs[nxt][lq + 3][lr] = bv.w;
            __syncthreads();
        }
    }

    // Epilogue: add bias, store (N=128 exactly, M divisible by 128 exactly)
    float bb[8];
#pragma unroll
    for (int j = 0; j < 8; ++j) bb[j] = bias[tx * 8 + j];

#pragma unroll
    for (int i = 0; i < 8; ++i) {
        float c[8];
#pragma unroll
        for (int j = 0; j < 4; ++j) unpack2(acc[i][j], c[2 * j], c[2 * j + 1]);
        float4 v0, v1;
        v0.x = c[0] + bb[0]; v0.y = c[1] + bb[1];
        v0.z = c[2] + bb[2]; v0.w = c[3] + bb[3];
        v1.x = c[4] + bb[4]; v1.y = c[5] + bb[5];
        v1.z = c[6] + bb[6]; v1.w = c[7] + bb[7];
        float* orow = out + (size_t)(m0 + ty * 8 + i) * COUT + tx * 8;
        *(float4*)(orow + 0) = v0;
        *(float4*)(orow + 4) = v1;
    }
}

// ---------------------------------------------------------------------------
extern "C" void kernel_launch(void* const* d_in, const int* in_sizes, int n_in,
                              void* d_out, int out_size)
{
    const float* input_feat = (const float*)d_in[0];
    const int*   nbr_raw    = (const int*)d_in[1];   // int32 or int64, detected
    const float* wnet       = (const float*)d_in[2];
    const float* addf       = (const float*)d_in[3];
    const float* W          = (const float*)d_in[4];
    const float* bias       = (const float*)d_in[5];
    float*       out        = (float*)d_out;

    detect_idx_kernel<<<1, 32>>>(nbr_raw);
    pconv_kernel<<<NPTS / 4, 128>>>(input_feat, nbr_raw, wnet, addf);
    gemm_kernel<<<NPTS / MS, 256>>>(W, bias, out);
}

// round 10
// speedup vs baseline: 2.6044x; 2.6044x over previous
#include <cuda_runtime.h>
#include <cuda_fp16.h>
#include <cstdint>

// Problem constants
#define BQ    2
#define NPT   65536
#define KN    16
#define CIN   64
#define CADD  3
#define CTOT  67
#define CPAD  68
#define CMID  16
#define INF   1072        // CTOT * CMID
#define KPAD  1088        // padded to 17*64
#define COUT  128
#define NPTS  (BQ * NPT)  // 131072

// fp16 scratch: pconv output [M][KPAD] (285 MB) + converted weights
__device__ __half g_a16[(size_t)NPTS * KPAD];
__device__ __half g_w16[(size_t)COUT * KPAD];
__device__ int g_idx_is64;

// ---------------------------------------------------------------------------
// Helpers
// ---------------------------------------------------------------------------
__device__ __forceinline__ uint32_t smem_u32(const void* p) {
    uint32_t a;
    asm("{ .reg .u64 t; cvta.to.shared.u64 t, %1; cvt.u32.u64 %0, t; }"
        : "=r"(a) : "l"(p));
    return a;
}
__device__ __forceinline__ uint32_t lds32(uint32_t a) {
    uint32_t v;
    asm volatile("ld.shared.b32 %0, [%1];" : "=r"(v) : "r"(a));
    return v;
}
__device__ __forceinline__ void cp16(uint32_t sa, const void* g) {
    asm volatile("cp.async.cg.shared.global [%0], [%1], 16;" :: "r"(sa), "l"(g));
}
#define CP_COMMIT() asm volatile("cp.async.commit_group;" ::: "memory")
#define CP_WAIT0()  asm volatile("cp.async.wait_group 0;" ::: "memory")

__device__ __forceinline__ void mma16816(float* c, uint32_t a0, uint32_t a1,
                                         uint32_t a2, uint32_t a3,
                                         uint32_t b0, uint32_t b1) {
    asm volatile(
        "mma.sync.aligned.m16n8k16.row.col.f32.f16.f16.f32 "
        "{%0,%1,%2,%3}, {%4,%5,%6,%7}, {%8,%9}, {%0,%1,%2,%3};"
        : "+f"(c[0]), "+f"(c[1]), "+f"(c[2]), "+f"(c[3])
        : "r"(a0), "r"(a1), "r"(a2), "r"(a3), "r"(b0), "r"(b1));
}

// ---------------------------------------------------------------------------
// Kernel 0: detect index dtype (int64 vs int32 layout). Values < 65536, so an
// int64 buffer has all-zero odd 32-bit words. Reads 128B, in-bounds either way.
// ---------------------------------------------------------------------------
__global__ void detect_idx_kernel(const int* __restrict__ idx_raw)
{
    if (threadIdx.x == 0 && blockIdx.x == 0) {
        int nz = 0;
#pragma unroll
        for (int i = 1; i < 32; i += 2) nz |= idx_raw[i];
        g_idx_is64 = (nz == 0) ? 1 : 0;
    }
}

// ---------------------------------------------------------------------------
// Kernel W: convert linear_weight to fp16, zero-padded to KPAD
// ---------------------------------------------------------------------------
__global__ void wconv_kernel(const float* __restrict__ W)
{
    int idx = blockIdx.x * 256 + threadIdx.x;
    if (idx >= COUT * KPAD) return;
    int row = idx / KPAD, col = idx % KPAD;
    float x = (col < INF) ? W[row * INF + col] : 0.f;
    g_w16[idx] = __float2half_rn(x);
}

// ---------------------------------------------------------------------------
// fp16 store of a 16-float block (32 B = 2 uint4)
// ---------------------------------------------------------------------------
__device__ __forceinline__ void store_half16(__half* dst, const float* a)
{
    uint32_t h[8];
#pragma unroll
    for (int q = 0; q < 8; ++q) {
        __half2 v = __float22half2_rn(make_float2(a[2 * q], a[2 * q + 1]));
        h[q] = *(uint32_t*)&v;
    }
    ((uint4*)dst)[0] = make_uint4(h[0], h[1], h[2], h[3]);
    ((uint4*)dst)[1] = make_uint4(h[4], h[5], h[6], h[7]);
}

// ---------------------------------------------------------------------------
// Kernel 1: gather + weighted neighbor reduction -> fp16 rows [KPAD]
// One warp per point; 4 points per 128-thread block.
// ---------------------------------------------------------------------------
__global__ void __launch_bounds__(128, 8)
pconv_kernel(const float* __restrict__ input_feat,
             const int* __restrict__ nbr_raw,
             const float* __restrict__ wnet,
             const float* __restrict__ addf)
{
    const int warp = threadIdx.x >> 5;
    const int lane = threadIdx.x & 31;
    const int p = blockIdx.x * 4 + warp;
    const int b = p >> 16;

    __shared__ __align__(16) float fs[4][KN][CPAD];
    __shared__ __align__(16) float ws[4][KN][CMID];

    const float* featbase = input_feat + (size_t)b * NPT * CIN;
    const float* wp = wnet + (size_t)p * KN * CMID;
    const float* ap = addf + (size_t)p * KN * CADD;

    {
        const float4* w4 = (const float4*)wp;
        float4* s4 = (float4*)(&ws[warp][0][0]);
        s4[lane]      = w4[lane];
        s4[lane + 32] = w4[lane + 32];
    }

    const int stride = g_idx_is64 ? 2 : 1;
    const int* inds = nbr_raw + (size_t)p * KN * stride;
    int myidx = 0;
    if (lane < KN) {
        myidx = inds[lane * stride];
        myidx = min(max(myidx, 0), NPT - 1);
    }

#pragma unroll 4
    for (int k = 0; k < KN; ++k) {
        int r = __shfl_sync(0xffffffffu, myidx, k);
        const float* src = featbase + (size_t)r * CIN;
        fs[warp][k][lane]      = src[lane];
        fs[warp][k][lane + 32] = src[lane + 32];
    }
    if (lane < KN) {
        fs[warp][lane][64] = ap[lane * 3 + 0];
        fs[warp][lane][65] = ap[lane * 3 + 1];
        fs[warp][lane][66] = ap[lane * 3 + 2];
    }
    __syncwarp();

    float acc0[CMID], acc1[CMID], acc2[CMID];
#pragma unroll
    for (int j = 0; j < CMID; ++j) { acc0[j] = 0.f; acc1[j] = 0.f; acc2[j] = 0.f; }

    const bool has_c2 = (lane < 3);
#pragma unroll
    for (int k = 0; k < KN; ++k) {
        float wk[CMID];
#pragma unroll
        for (int j = 0; j < CMID; ++j) wk[j] = ws[warp][k][j];
        float f0 = fs[warp][k][lane];
        float f1 = fs[warp][k][lane + 32];
        float f2 = has_c2 ? fs[warp][k][lane + 64] : 0.f;
#pragma unroll
        for (int j = 0; j < CMID; ++j) {
            acc0[j] += f0 * wk[j];
            acc1[j] += f1 * wk[j];
            acc2[j] += f2 * wk[j];
        }
    }

    __half* orow = g_a16 + (size_t)p * KPAD;
    store_half16(orow + (size_t)lane * CMID,        acc0);
    store_half16(orow + (size_t)(lane + 32) * CMID, acc1);
    if (has_c2)
        store_half16(orow + (size_t)(lane + 64) * CMID, acc2);
    if (lane == 3) {   // zero pad cols 1072..1087
        uint4 z = make_uint4(0, 0, 0, 0);
        ((uint4*)(orow + INF))[0] = z;
        ((uint4*)(orow + INF))[1] = z;
    }
}

// ---------------------------------------------------------------------------
// Kernel 2: fp16 mma.sync GEMM   out[M,128] = A[M,KPAD] @ W[128,KPAD]^T + bias
// CTA 128x128, 8 warps (2x4), warp tile 64x32 = 4x4 m16n8k16 frags, fp32 acc.
// K staged 64-wide, double-buffered via cp.async. SMEM pitch 144B (bank-clean).
// ---------------------------------------------------------------------------
#define KSTG   64
#define PITCH  144                    // bytes per smem row (72 halves)
#define TILEB  (128 * PITCH)          // 18432 B per matrix per stage
#define OFF_A  0
#define OFF_W  (2 * TILEB)            // A double-buffer first
#define OFF_BIAS (4 * TILEB)
#define SMEM_BYTES (4 * TILEB + 512)  // 74240
#define NSTG   (KPAD / KSTG)          // 17

__global__ void __launch_bounds__(256, 2)
gemm_mma_kernel(const float* __restrict__ bias, float* __restrict__ out)
{
    extern __shared__ char smem[];
    const uint32_t sb = smem_u32(smem);
    const int t = threadIdx.x;
    const int wid = t >> 5, lane = t & 31;
    const int wm = wid >> 2, wn = wid & 3;          // warp grid 2(M) x 4(N)
    const int g = lane >> 2, tg = lane & 3;         // mma lane decomposition
    const int m0 = blockIdx.x * 128;

    if (t < COUT) ((float*)(smem + OFF_BIAS))[t] = bias[t];

    // per-thread load slots: 4 x 16B for A, 4 x 16B for W per stage
    const int lrow = t >> 1;                        // 0..127
    const int lc8a = (t & 1) * 4;                   // base c8 for this thread (0 or 4)

    auto issue_stage = [&](int s, int buf) {
        const int k0 = s * KSTG;
#pragma unroll
        for (int i = 0; i < 4; ++i) {
            const int c8 = lc8a + i;                // 0..7, 8 halves each
            const uint32_t so = lrow * PITCH + c8 * 16;
            cp16(sb + OFF_A + buf * TILEB + so,
                 g_a16 + (size_t)(m0 + lrow) * KPAD + k0 + c8 * 8);
            cp16(sb + OFF_W + buf * TILEB + so,
                 g_w16 + (size_t)lrow * KPAD + k0 + c8 * 8);
        }
        CP_COMMIT();
    };

    float acc[4][4][4];
#pragma unroll
    for (int mi = 0; mi < 4; ++mi)
#pragma unroll
        for (int ni = 0; ni < 4; ++ni)
#pragma unroll
            for (int q = 0; q < 4; ++q) acc[mi][ni][q] = 0.f;

    issue_stage(0, 0);
    CP_WAIT0();
    __syncthreads();

    for (int s = 0; s < NSTG; ++s) {
        const int cur = s & 1, nxt = cur ^ 1;
        if (s + 1 < NSTG) issue_stage(s + 1, nxt);

        const uint32_t aB = sb + OFF_A + cur * TILEB + (wm * 64 + g) * PITCH + tg * 4;
        const uint32_t bB = sb + OFF_W + cur * TILEB + (wn * 32 + g) * PITCH + tg * 4;
#pragma unroll
        for (int kk = 0; kk < 4; ++kk) {            // 4 k16-steps per stage
            const uint32_t ka = aB + kk * 32;       // 16 halves = 32 B
            const uint32_t kb = bB + kk * 32;
            uint32_t a[4][4], bfr[4][2];
#pragma unroll
            for (int mi = 0; mi < 4; ++mi) {
                const uint32_t r = ka + mi * 16 * PITCH;
                a[mi][0] = lds32(r);
                a[mi][1] = lds32(r + 8 * PITCH);
                a[mi][2] = lds32(r + 16);
                a[mi][3] = lds32(r + 8 * PITCH + 16);
            }
#pragma unroll
            for (int ni = 0; ni < 4; ++ni) {
                const uint32_t r = kb + ni * 8 * PITCH;
                bfr[ni][0] = lds32(r);
                bfr[ni][1] = lds32(r + 16);
            }
#pragma unroll
            for (int mi = 0; mi < 4; ++mi)
#pragma unroll
                for (int ni = 0; ni < 4; ++ni)
                    mma16816(acc[mi][ni], a[mi][0], a[mi][1], a[mi][2], a[mi][3],
                             bfr[ni][0], bfr[ni][1]);
        }
        CP_WAIT0();
        __syncthreads();
    }

    // Epilogue: bias + store. c frag: rows g, g+8; cols tg*2, tg*2+1.
    const float* sbias = (const float*)(smem + OFF_BIAS);
#pragma unroll
    for (int mi = 0; mi < 4; ++mi) {
        const int r0 = m0 + wm * 64 + mi * 16 + g;
#pragma unroll
        for (int ni = 0; ni < 4; ++ni) {
            const int c = wn * 32 + ni * 8 + tg * 2;
            const float b0 = sbias[c], b1 = sbias[c + 1];
            float2 v0 = make_float2(acc[mi][ni][0] + b0, acc[mi][ni][1] + b1);
            float2 v1 = make_float2(acc[mi][ni][2] + b0, acc[mi][ni][3] + b1);
            *(float2*)(out + (size_t)r0 * COUT + c)       = v0;
            *(float2*)(out + (size_t)(r0 + 8) * COUT + c) = v1;
        }
    }
}

// ---------------------------------------------------------------------------
extern "C" void kernel_launch(void* const* d_in, const int* in_sizes, int n_in,
                              void* d_out, int out_size)
{
    const float* input_feat = (const float*)d_in[0];
    const int*   nbr_raw    = (const int*)d_in[1];
    const float* wnet       = (const float*)d_in[2];
    const float* addf       = (const float*)d_in[3];
    const float* W          = (const float*)d_in[4];
    const float* bias       = (const float*)d_in[5];
    float*       out        = (float*)d_out;

    static bool attr_set = false;
    if (!attr_set) {
        cudaFuncSetAttribute(gemm_mma_kernel,
                             cudaFuncAttributeMaxDynamicSharedMemorySize, SMEM_BYTES);
        attr_set = true;
    }

    detect_idx_kernel<<<1, 32>>>(nbr_raw);
    wconv_kernel<<<(COUT * KPAD + 255) / 256, 256>>>(W);
    pconv_kernel<<<NPTS / 4, 128>>>(input_feat, nbr_raw, wnet, addf);
    gemm_mma_kernel<<<NPTS / 128, 256, SMEM_BYTES>>>(bias, out);
}